// round 2
// baseline (speedup 1.0000x reference)
#include <cuda_runtime.h>
#include <cuda_bf16.h>

// U1_circuit: 5-qubit quanvolution simulator.
// One thread per (pixel, filter) simulation; 32-amplitude complex state in registers.
//
// inputs: (32,32,32,3) f32   kernel: (8,1,15) f32   out: (32,31,31,8) f32
//
// Qubit bit map (state index m, 5 bits): qubit0 -> bit4 (16), qubit(1+i) -> bit(3-i) (8>>i).

#define NB 32   // batch
#define NH 32
#define NW 32
#define NC 3
#define NY 31
#define NX 31
#define NF 8

__global__ void __launch_bounds__(128)
qsim_kernel(const float* __restrict__ inp,
            const float* __restrict__ ker,
            float* __restrict__ out,
            int total)
{
    int t = blockIdx.x * blockDim.x + threadIdx.x;
    if (t >= total) return;

    const int f   = t & (NF - 1);
    const int pix = t >> 3;
    const int x   = pix % NX;
    const int y   = (pix / NX) % NY;
    const int b   = pix / (NX * NY);

    // angles[j][i]: channel j, corner i of the 2x2 patch at (y, x)
    float ang[3][4];
#pragma unroll
    for (int i = 0; i < 4; i++) {
        const int yy = y + (i >> 1);
        const int xx = x + (i & 1);
        const float* p = inp + ((size_t)(b * NH + yy) * NW + xx) * NC;
#pragma unroll
        for (int j = 0; j < 3; j++) ang[j][i] = p[j];
    }

    // filter params: kernel[f, 0, 0..14]
    const float* pr = ker + f * 15;

    // state: 32 complex amplitudes in registers
    float sr[32], si[32];
#pragma unroll
    for (int m = 0; m < 32; m++) { sr[m] = 0.f; si[m] = 0.f; }
    const float IS2 = 0.70710678118654752440f;
    sr[0]  = IS2;   // H on qubit 0 applied to |00000>
    sr[16] = IS2;

#pragma unroll
    for (int j = 0; j < 3; j++) {
        // ---- RX(pi*ang) on qubits 1..4 (bits 8,4,2,1) ----
#pragma unroll
        for (int i = 0; i < 4; i++) {
            float sn, cs;
            sincospif(0.5f * ang[j][i], &sn, &cs);   // cos/sin(theta/2), theta = pi*ang
            const int bit = 8 >> i;
#pragma unroll
            for (int m = 0; m < 32; m++) {
                if (m & bit) continue;
                const int m1 = m | bit;
                const float a0r = sr[m],  a0i = si[m];
                const float a1r = sr[m1], a1i = si[m1];
                // [[c, -i s],[-i s, c]]
                sr[m]  = cs * a0r + sn * a1i;
                si[m]  = cs * a0i - sn * a1r;
                sr[m1] = cs * a1r + sn * a0i;
                si[m1] = cs * a1i - sn * a0r;
            }
        }

        // ---- CX^p on (1,2),(2,3),(3,4),(4,1) ----
        const int bc[4] = {8, 4, 2, 1};
        const int bt[4] = {4, 2, 1, 8};
#pragma unroll
        for (int g = 0; g < 4; g++) {
            float li, lr;
            sincospif(pr[5 * j + g], &li, &lr);      // lambda = exp(i*pi*p)
            const float arr = 0.5f * (1.f + lr), aii = 0.5f * li;
            const float brr = 0.5f * (1.f - lr), bii = -0.5f * li;
            const int Bc = bc[g], Bt = bt[g];
#pragma unroll
            for (int m = 0; m < 32; m++) {
                if (!(m & Bc) || (m & Bt)) continue;  // control=1, target=0
                const int m1 = m | Bt;
                const float xr = sr[m],  xi = si[m];
                const float yr = sr[m1], yi = si[m1];
                sr[m]  = arr * xr - aii * xi + brr * yr - bii * yi;
                si[m]  = arr * xi + aii * xr + brr * yi + bii * yr;
                sr[m1] = brr * xr - bii * xi + arr * yr - aii * yi;
                si[m1] = brr * xi + bii * xr + arr * yi + aii * yr;
            }
        }

        // ---- CZ^p on (1,0): amplitudes with bits 8 and 16 both set ----
        {
            float li, lr;
            sincospif(pr[5 * j + 4], &li, &lr);
#pragma unroll
            for (int m = 0; m < 32; m++) {
                if ((m & 24) != 24) continue;
                const float xr = sr[m], xi = si[m];
                sr[m] = lr * xr - li * xi;
                si[m] = lr * xi + li * xr;
            }
        }
    }

    // exp = 2 * sum_m Re(conj(s[m]) * s[m+16])
    float e = 0.f;
#pragma unroll
    for (int m = 0; m < 16; m++) e += sr[m] * sr[m + 16] + si[m] * si[m + 16];
    e *= 2.f;
    e = fminf(fmaxf(e, -1.f + 1e-5f), 1.f - 1e-5f);
    out[t] = acosf(e) * 0.31830988618379067154f;   // / pi
}

extern "C" void kernel_launch(void* const* d_in, const int* in_sizes, int n_in,
                              void* d_out, int out_size)
{
    const float* inp = (const float*)d_in[0];
    const float* ker = (const float*)d_in[1];
    float* out = (float*)d_out;
    const int total = NB * NY * NX * NF;   // 246016 == out_size
    const int threads = 128;
    const int blocks = (total + threads - 1) / threads;
    qsim_kernel<<<blocks, threads>>>(inp, ker, out, total);
}

// round 3
// speedup vs baseline: 1.6066x; 1.6066x over previous
#include <cuda_runtime.h>
#include <cuda_bf16.h>

// U1_circuit: 5-qubit quanvolution simulator, v2.
// One thread per (pixel, filter). Block = 128 threads = 16 pixels x 8 filters.
// Trig precomputed cooperatively into shared memory; CX^p uses the
// x' = x + b(y-x) identity (10 ops/pair instead of 16).
//
// inputs: (32,32,32,3) f32   kernel: (8,1,15) f32   out: (32,31,31,8) f32
// Qubit bit map: qubit0 -> bit 16, qubit(1+i) -> bit (8>>i).

#define NB 32
#define NH 32
#define NW 32
#define NC 3
#define NY 31
#define NX 31
#define NF 8

#define PIX_PER_BLK 16
#define THREADS 128

__global__ void __launch_bounds__(THREADS)
qsim_kernel(const float* __restrict__ inp,
            const float* __restrict__ ker,
            float* __restrict__ out)
{
    __shared__ float2 s_rx[PIX_PER_BLK][12];  // (sn, cs) per pixel, gate j*4+i
    __shared__ float2 s_cx[NF][12];           // (br, bi) per filter, gate j*4+g
    __shared__ float2 s_cz[NF][3];            // (lr, li) per filter, layer j

    const int tid  = threadIdx.x;
    const int pix0 = blockIdx.x * PIX_PER_BLK;

    // ---- cooperative precompute: RX angles (16 pixels x 12 gates) ----
#pragma unroll
    for (int k = tid; k < PIX_PER_BLK * 12; k += THREADS) {
        const int pl  = k / 12;
        const int g   = k - pl * 12;
        const int pix = pix0 + pl;
        const int x   = pix % NX;
        const int y   = (pix / NX) % NY;
        const int b   = pix / (NX * NY);
        const int i   = g & 3;        // corner
        const int j   = g >> 2;       // channel / layer
        const int yy  = y + (i >> 1);
        const int xx  = x + (i & 1);
        const float a = inp[((size_t)(b * NH + yy) * NW + xx) * NC + j];
        float sn, cs;
        sincospif(0.5f * a, &sn, &cs);
        s_rx[pl][g] = make_float2(sn, cs);
    }

    // ---- cooperative precompute: filter params (8 filters x 15) ----
    if (tid < NF * 15) {
        const int f = tid / 15;
        const int q = tid - f * 15;
        const float p = ker[f * 15 + q];
        float li, lr;
        sincospif(p, &li, &lr);              // lambda = exp(i*pi*p)
        const int j  = q / 5;
        const int q5 = q - j * 5;
        if (q5 < 4) {
            // b = (1 - lambda)/2
            s_cx[f][j * 4 + q5] = make_float2(0.5f * (1.f - lr), -0.5f * li);
        } else {
            s_cz[f][j] = make_float2(lr, li);
        }
    }
    __syncthreads();

    const int pl = tid >> 3;       // local pixel
    const int f  = tid & (NF - 1); // filter

    // ---- state: 32 complex amplitudes in registers ----
    float sr[32], si[32];
#pragma unroll
    for (int m = 0; m < 32; m++) { sr[m] = 0.f; si[m] = 0.f; }
    const float IS2 = 0.70710678118654752440f;
    sr[0]  = IS2;
    sr[16] = IS2;

#pragma unroll
    for (int j = 0; j < 3; j++) {
        // ---- RX(pi*ang) on qubits 1..4 (bits 8,4,2,1) ----
#pragma unroll
        for (int i = 0; i < 4; i++) {
            const float2 sc = s_rx[pl][j * 4 + i];
            const float sn = sc.x, cs = sc.y;
            const int bit = 8 >> i;
#pragma unroll
            for (int m = 0; m < 32; m++) {
                if (m & bit) continue;
                const int m1 = m | bit;
                const float a0r = sr[m],  a0i = si[m];
                const float a1r = sr[m1], a1i = si[m1];
                sr[m]  = cs * a0r + sn * a1i;
                si[m]  = cs * a0i - sn * a1r;
                sr[m1] = cs * a1r + sn * a0i;
                si[m1] = cs * a1i - sn * a0r;
            }
        }

        // ---- CX^p: x' = x + b(y-x), y' = y - b(y-x) ----
        const int bc[4] = {8, 4, 2, 1};
        const int bt[4] = {4, 2, 1, 8};
#pragma unroll
        for (int g = 0; g < 4; g++) {
            const float2 bb = s_cx[f][j * 4 + g];
            const float br = bb.x, bi = bb.y;
            const int Bc = bc[g], Bt = bt[g];
#pragma unroll
            for (int m = 0; m < 32; m++) {
                if (!(m & Bc) || (m & Bt)) continue;   // control=1, target=0
                const int m1 = m | Bt;
                const float dr = sr[m1] - sr[m];
                const float di = si[m1] - si[m];
                const float er = br * dr - bi * di;
                const float ei = br * di + bi * dr;
                sr[m]  += er;  si[m]  += ei;
                sr[m1] -= er;  si[m1] -= ei;
            }
        }

        // ---- CZ^p on (1,0): bits 8 and 16 both set ----
        {
            const float2 ll = s_cz[f][j];
            const float lr = ll.x, li = ll.y;
#pragma unroll
            for (int m = 0; m < 32; m++) {
                if ((m & 24) != 24) continue;
                const float xr = sr[m], xi = si[m];
                sr[m] = lr * xr - li * xi;
                si[m] = lr * xi + li * xr;
            }
        }
    }

    // ---- exp = 2 * sum Re(conj(s[m]) * s[m+16]) ----
    float e = 0.f;
#pragma unroll
    for (int m = 0; m < 16; m++) e += sr[m] * sr[m + 16] + si[m] * si[m + 16];
    e *= 2.f;
    e = fminf(fmaxf(e, -1.f + 1e-5f), 1.f - 1e-5f);
    out[blockIdx.x * THREADS + tid] = acosf(e) * 0.31830988618379067154f;
}

extern "C" void kernel_launch(void* const* d_in, const int* in_sizes, int n_in,
                              void* d_out, int out_size)
{
    const float* inp = (const float*)d_in[0];
    const float* ker = (const float*)d_in[1];
    float* out = (float*)d_out;
    const int total = NB * NY * NX * NF;        // 246016
    const int blocks = total / THREADS;         // 1922 exactly
    qsim_kernel<<<blocks, THREADS>>>(inp, ker, out);
}

// round 4
// speedup vs baseline: 1.6245x; 1.0111x over previous
#include <cuda_runtime.h>
#include <cuda_bf16.h>

// U1_circuit v3: qubit-0 (bit 16) is a spectator for all RX/CX gates, so the
// state is packed as 16 f32x2 pairs (m, m+16) and evolved with packed
// fma.rn.f32x2 (FFMA2) — one issue slot = two FMAs. CZ(1,0) uses lane-masked
// packed constants (1,lr)/(0,li).
//
// inputs: (32,32,32,3) f32   kernel: (8,1,15) f32   out: (32,31,31,8) f32

#define NB 32
#define NH 32
#define NW 32
#define NC 3
#define NY 31
#define NX 31
#define NF 8

#define PIX_PER_BLK 16
#define THREADS 128

typedef unsigned long long u64;

__device__ __forceinline__ u64 pk(float lo, float hi) {
    u64 r; asm("mov.b64 %0, {%1, %2};" : "=l"(r) : "f"(lo), "f"(hi)); return r;
}
__device__ __forceinline__ void unpk(float& lo, float& hi, u64 v) {
    asm("mov.b64 {%0, %1}, %2;" : "=f"(lo), "=f"(hi) : "l"(v));
}
__device__ __forceinline__ u64 bc2(float x) { return pk(x, x); }
__device__ __forceinline__ u64 ffma2(u64 a, u64 b, u64 c) {
    u64 d; asm("fma.rn.f32x2 %0, %1, %2, %3;" : "=l"(d) : "l"(a), "l"(b), "l"(c)); return d;
}
__device__ __forceinline__ u64 fmul2(u64 a, u64 b) {
    u64 d; asm("mul.rn.f32x2 %0, %1, %2;" : "=l"(d) : "l"(a), "l"(b)); return d;
}
__device__ __forceinline__ u64 fadd2(u64 a, u64 b) {
    u64 d; asm("add.rn.f32x2 %0, %1, %2;" : "=l"(d) : "l"(a), "l"(b)); return d;
}

__global__ void __launch_bounds__(THREADS)
qsim_kernel(const float* __restrict__ inp,
            const float* __restrict__ ker,
            float* __restrict__ out)
{
    __shared__ float2 s_rx[PIX_PER_BLK][12];  // (sn, cs) per pixel, gate j*4+i
    __shared__ float2 s_cx[NF][12];           // (br, bi) per filter, gate j*4+g
    __shared__ float2 s_cz[NF][3];            // (lr, li) per filter, layer j

    const int tid  = threadIdx.x;
    const int pix0 = blockIdx.x * PIX_PER_BLK;

    // ---- cooperative precompute: RX angles (16 pixels x 12 gates) ----
#pragma unroll
    for (int k = tid; k < PIX_PER_BLK * 12; k += THREADS) {
        const int pl  = k / 12;
        const int g   = k - pl * 12;
        const int pix = pix0 + pl;
        const int x   = pix % NX;
        const int y   = (pix / NX) % NY;
        const int b   = pix / (NX * NY);
        const int i   = g & 3;
        const int j   = g >> 2;
        const int yy  = y + (i >> 1);
        const int xx  = x + (i & 1);
        const float a = inp[((size_t)(b * NH + yy) * NW + xx) * NC + j];
        float sn, cs;
        sincospif(0.5f * a, &sn, &cs);
        s_rx[pl][g] = make_float2(sn, cs);
    }

    // ---- cooperative precompute: filter params (8 filters x 15) ----
    if (tid < NF * 15) {
        const int f = tid / 15;
        const int q = tid - f * 15;
        const float p = ker[f * 15 + q];
        float li, lr;
        sincospif(p, &li, &lr);              // lambda = exp(i*pi*p)
        const int j  = q / 5;
        const int q5 = q - j * 5;
        if (q5 < 4) {
            s_cx[f][j * 4 + q5] = make_float2(0.5f * (1.f - lr), -0.5f * li);
        } else {
            s_cz[f][j] = make_float2(lr, li);
        }
    }
    __syncthreads();

    const int pl = tid >> 3;
    const int f  = tid & (NF - 1);

    // ---- packed state: lane0 = amplitude m, lane1 = amplitude m+16 ----
    u64 R[16], I[16];
#pragma unroll
    for (int m = 0; m < 16; m++) { R[m] = 0ull; I[m] = 0ull; }
    const float IS2 = 0.70710678118654752440f;
    R[0] = pk(IS2, IS2);   // H|0> on qubit 0

    const u64 neg1 = bc2(-1.0f);

#pragma unroll
    for (int j = 0; j < 3; j++) {
        // ---- RX(pi*ang) on qubits 1..4 (bits 8,4,2,1 of m) ----
#pragma unroll
        for (int i = 0; i < 4; i++) {
            const float2 sc = s_rx[pl][j * 4 + i];
            const u64 sn2  = bc2(sc.x);
            const u64 nsn2 = bc2(-sc.x);
            const u64 cs2  = bc2(sc.y);
            const int bit = 8 >> i;
#pragma unroll
            for (int m = 0; m < 16; m++) {
                if (m & bit) continue;
                const int m1 = m | bit;
                const u64 r0 = R[m],  i0 = I[m];
                const u64 r1 = R[m1], i1 = I[m1];
                R[m]  = ffma2(cs2, r0, fmul2(sn2,  i1));
                I[m]  = ffma2(cs2, i0, fmul2(nsn2, r1));
                R[m1] = ffma2(cs2, r1, fmul2(sn2,  i0));
                I[m1] = ffma2(cs2, i1, fmul2(nsn2, r0));
            }
        }

        // ---- CX^p: x' = x + b(y-x), y' = y - b(y-x) ----
        const int bcb[4] = {8, 4, 2, 1};
        const int btb[4] = {4, 2, 1, 8};
#pragma unroll
        for (int g = 0; g < 4; g++) {
            const float2 bb = s_cx[f][j * 4 + g];
            const u64 br2  = bc2(bb.x);
            const u64 bi2  = bc2(bb.y);
            const u64 nbi2 = bc2(-bb.y);
            const int Bc = bcb[g], Bt = btb[g];
#pragma unroll
            for (int m = 0; m < 16; m++) {
                if (!(m & Bc) || (m & Bt)) continue;   // control=1, target=0
                const int m1 = m | Bt;
                const u64 dR = ffma2(R[m], neg1, R[m1]);   // R1 - R0
                const u64 dI = ffma2(I[m], neg1, I[m1]);
                const u64 eR = ffma2(br2, dR, fmul2(nbi2, dI));
                const u64 eI = ffma2(br2, dI, fmul2(bi2,  dR));
                R[m]  = fadd2(R[m],  eR);
                I[m]  = fadd2(I[m],  eI);
                R[m1] = ffma2(eR, neg1, R[m1]);
                I[m1] = ffma2(eI, neg1, I[m1]);
            }
        }

        // ---- CZ^p on (1,0): needs bit8 (m>=8) AND bit16 (hi lane only) ----
        {
            const float2 ll = s_cz[f][j];
            const u64 Lr  = pk(1.0f,  ll.x);
            const u64 Li  = pk(0.0f,  ll.y);
            const u64 nLi = pk(0.0f, -ll.y);
#pragma unroll
            for (int m = 8; m < 16; m++) {
                const u64 xr = R[m], xi = I[m];
                R[m] = ffma2(Lr, xr, fmul2(nLi, xi));
                I[m] = ffma2(Lr, xi, fmul2(Li,  xr));
            }
        }
    }

    // ---- exp = 2 * sum_m (sr[m]*sr[m+16] + si[m]*si[m+16]) ----
    float e = 0.f;
#pragma unroll
    for (int m = 0; m < 16; m++) {
        float rl, rh, il, ih;
        unpk(rl, rh, R[m]);
        unpk(il, ih, I[m]);
        e += rl * rh + il * ih;
    }
    e *= 2.f;
    e = fminf(fmaxf(e, -1.f + 1e-5f), 1.f - 1e-5f);
    out[blockIdx.x * THREADS + tid] = acosf(e) * 0.31830988618379067154f;
}

extern "C" void kernel_launch(void* const* d_in, const int* in_sizes, int n_in,
                              void* d_out, int out_size)
{
    const float* inp = (const float*)d_in[0];
    const float* ker = (const float*)d_in[1];
    float* out = (float*)d_out;
    const int total = NB * NY * NX * NF;        // 246016
    const int blocks = total / THREADS;         // 1922 exactly
    qsim_kernel<<<blocks, THREADS>>>(inp, ker, out);
}